// round 6
// baseline (speedup 1.0000x reference)
#include <cuda_runtime.h>
#include <cstdint>

#define J   17
#define E   4096
#define M16 16
#define K1  (2*E)       // 8192
#define K2  E           // 4096
#define TK1 256         // GEMM1: 32 slabs, grid (4,32)=128
#define TK2 128         // GEMM2: 32 slabs, grid (4,32)=128
#define NSLAB 32
#define NBLK 128        // total CTAs per layer kernel (single wave, <=148)
#define LN_EPS 1e-5f

typedef unsigned long long ull;

// -------- device scratch --------
__device__ float    d_h[M16 * E];                // 256 KB hidden
__device__ float    d_partial[NSLAB * M16 * E];  // 8 MB
__device__ float2   d_stats[M16 * 8];            // per-(row,chunk) sum/sumsq
__device__ unsigned d_ctr[4];                    // grid-sync counters

__device__ __forceinline__ void fma2(ull& d, ull a, ull b) {
    asm("fma.rn.f32x2 %0, %1, %2, %0;" : "+l"(d) : "l"(a), "l"(b));
}
__device__ __forceinline__ ull dup_pack(float p) {
    unsigned int u = __float_as_uint(p);
    return ((ull)u << 32) | (ull)u;
}

// ============================================================
// L2-normalize joints (scale sqrt(E)=64) + zero sync counters.
// grid=17, block=256.
// ============================================================
__global__ void __launch_bounds__(256) normalize_kernel(
    const float* __restrict__ x, float* __restrict__ out_joint)
{
    if (blockIdx.x == 0 && threadIdx.x < 4) d_ctr[threadIdx.x] = 0u;

    int row = blockIdx.x;
    int tid = threadIdx.x;
    const float* xr = x + (size_t)row * E;

    float s = 0.f;
    float v[E / 256];
    #pragma unroll
    for (int i = 0; i < E / 256; i++) {
        v[i] = xr[tid + i * 256];
        s += v[i] * v[i];
    }
    __shared__ float red[256];
    red[tid] = s;
    __syncthreads();
    for (int off = 128; off > 0; off >>= 1) {
        if (tid < off) red[tid] += red[tid + off];
        __syncthreads();
    }
    __shared__ float s_inv;
    if (tid == 0) s_inv = 64.0f / fmaxf(sqrtf(red[0]), 1e-12f);
    __syncthreads();
    float inv = s_inv;
    #pragma unroll
    for (int i = 0; i < E / 256; i++)
        out_joint[(size_t)row * E + tid + i * 256] = v[i] * inv;
}

// ---- grid-wide sync (all NBLK CTAs resident: grid < SM count) ----
__device__ __forceinline__ void grid_sync(unsigned* ctr) {
    __syncthreads();
    if (threadIdx.x == 0) {
        __threadfence();
        atomicAdd(ctr, 1u);
        while (atomicAdd(ctr, 0u) < (unsigned)NBLK) { }
    }
    __syncthreads();
    __threadfence();
}

// ============================================================
// Fused layer: split-K GEMM -> sync -> reduce(+bias) -> sync -> LN apply.
// grid=(4, NSLAB)=128 CTAs, block=256.
// Warp w: col-block w>>1 (8 cols/thread), m-half (w&1)*8 (8 bones).
// MODE 0: gather pair act from joint+bone_pairs; MODE 1: from linear h.
// ============================================================
template<int TK, int MODE, bool RELU>
__global__ void __launch_bounds__(256) layer_kernel(
    const float* __restrict__ W,
    const float* __restrict__ act,
    const int*   __restrict__ bp,
    const float* __restrict__ bias,
    const float* __restrict__ gamma,
    const float* __restrict__ beta,
    float* __restrict__ outp,
    unsigned* ctrA, unsigned* ctrB)
{
    __shared__ union SmemU {
        ull sp[TK * M16];
        struct { float4 buf[128]; float rs[128]; float rq[128]; } b;
    } su;

    int tid = threadIdx.x;
    int k0 = blockIdx.y * TK;

    // ---- activation slab fill (gather + duplicate) ----
    {
        int m = tid & 15;
        const float* r0;
        const float* r1;
        if (MODE == 0) {
            r0 = act + (size_t)bp[2 * m] * E;
            r1 = act + (size_t)bp[2 * m + 1] * E;
        } else {
            r0 = act + (size_t)m * E;
            r1 = r0;
        }
        #pragma unroll
        for (int i = 0; i < (TK * M16) / 256; i++) {
            int kl = (tid >> 4) + i * 16;
            int k = k0 + kl;
            float p;
            if (MODE == 0) {
                int col = k & (E - 1);
                p = (k < E) ? r0[col] : r1[col];
            } else {
                p = r0[k];
            }
            su.sp[kl * M16 + m] = dup_pack(p);
        }
    }
    __syncthreads();

    // ---- GEMM mainloop ----
    int wid  = tid >> 5;
    int lane = tid & 31;
    int mh   = (wid & 1) * 8;                 // bone half
    int n    = blockIdx.x * 1024 + (wid >> 1) * 256 + lane * 8;
    const float* wp = W + (size_t)k0 * E + n;

    ull acc[8][4];
    #pragma unroll
    for (int m = 0; m < 8; m++)
        #pragma unroll
        for (int c = 0; c < 4; c++) acc[m][c] = 0ULL;

    #pragma unroll 1
    for (int kb = 0; kb < TK; kb += 4) {
        ulonglong2 wa[4], wb[4];
        #pragma unroll
        for (int s = 0; s < 4; s++) {
            const float* wr = wp + (size_t)(kb + s) * E;
            wa[s] = *reinterpret_cast<const ulonglong2*>(wr);
            wb[s] = *reinterpret_cast<const ulonglong2*>(wr + 4);
        }
        #pragma unroll
        for (int s = 0; s < 4; s++) {
            const ulonglong2* row =
                reinterpret_cast<const ulonglong2*>(su.sp + (kb + s) * M16 + mh);
            #pragma unroll
            for (int q = 0; q < 4; q++) {
                ulonglong2 r = row[q];         // {p,p} for bones mh+2q, mh+2q+1
                fma2(acc[2*q  ][0], wa[s].x, r.x);
                fma2(acc[2*q  ][1], wa[s].y, r.x);
                fma2(acc[2*q  ][2], wb[s].x, r.x);
                fma2(acc[2*q  ][3], wb[s].y, r.x);
                fma2(acc[2*q+1][0], wa[s].x, r.y);
                fma2(acc[2*q+1][1], wa[s].y, r.y);
                fma2(acc[2*q+1][2], wb[s].x, r.y);
                fma2(acc[2*q+1][3], wb[s].y, r.y);
            }
        }
    }

    // ---- write partials: [slab][m][E] ----
    {
        size_t base = ((size_t)blockIdx.y * M16 + mh) * E + n;
        #pragma unroll
        for (int m = 0; m < 8; m++) {
            ulonglong2 o0; o0.x = acc[m][0]; o0.y = acc[m][1];
            ulonglong2 o1; o1.x = acc[m][2]; o1.y = acc[m][3];
            *reinterpret_cast<ulonglong2*>(&d_partial[base + (size_t)m * E])     = o0;
            *reinterpret_cast<ulonglong2*>(&d_partial[base + (size_t)m * E + 4]) = o1;
        }
    }

    grid_sync(ctrA);

    // ---- split-K reduce + bias (values kept in registers) ----
    int flat = blockIdx.y * 4 + blockIdx.x;       // 0..127
    int mrow = flat >> 3;
    int ch   = flat & 7;
    int c4   = tid & 127;
    int half = tid >> 7;
    int n4   = ch * 128 + c4;                     // float4 column, 0..1023

    const float4* p4 = reinterpret_cast<const float4*>(d_partial)
                     + (size_t)mrow * (E / 4) + n4;
    const size_t stride = (size_t)M16 * (E / 4);

    float4 v = (half == 0)
             ? reinterpret_cast<const float4*>(bias)[n4]
             : make_float4(0.f, 0.f, 0.f, 0.f);
    {
        int s0 = half * 16;
        float4 a[4];
        a[0] = v;
        #pragma unroll
        for (int r = 1; r < 4; r++) a[r] = make_float4(0.f, 0.f, 0.f, 0.f);
        #pragma unroll
        for (int ks = 0; ks < 16; ks += 4) {
            #pragma unroll
            for (int r = 0; r < 4; r++) {
                float4 t = p4[(size_t)(s0 + ks + r) * stride];
                a[r].x += t.x; a[r].y += t.y; a[r].z += t.z; a[r].w += t.w;
            }
        }
        a[0].x += a[1].x; a[0].y += a[1].y; a[0].z += a[1].z; a[0].w += a[1].w;
        a[2].x += a[3].x; a[2].y += a[3].y; a[2].z += a[3].z; a[2].w += a[3].w;
        v.x = a[0].x + a[2].x; v.y = a[0].y + a[2].y;
        v.z = a[0].z + a[2].z; v.w = a[0].w + a[2].w;
    }
    __syncthreads();   // smem union: sp dead, switch to b
    if (half == 1) su.b.buf[c4] = v;
    __syncthreads();
    if (half == 0) {
        float4 o = su.b.buf[c4];
        v.x += o.x; v.y += o.y; v.z += o.z; v.w += o.w;
        su.b.rs[c4] = (v.x + v.y) + (v.z + v.w);
        su.b.rq[c4] = (v.x * v.x + v.y * v.y) + (v.z * v.z + v.w * v.w);
    }
    __syncthreads();
    for (int off = 64; off > 0; off >>= 1) {
        if (tid < off) {
            su.b.rs[tid] += su.b.rs[tid + off];
            su.b.rq[tid] += su.b.rq[tid + off];
        }
        __syncthreads();
    }
    if (tid == 0)
        d_stats[mrow * 8 + ch] = make_float2(su.b.rs[0], su.b.rq[0]);

    grid_sync(ctrB);

    // ---- finalize LN stats + apply ----
    if (half == 0) {
        float sum = 0.f, sq = 0.f;
        #pragma unroll
        for (int c = 0; c < 8; c++) {
            float2 s = d_stats[mrow * 8 + c];
            sum += s.x; sq += s.y;
        }
        float mu   = sum * (1.0f / E);
        float var  = sq * (1.0f / E) - mu * mu;
        float rstd = rsqrtf(var + LN_EPS);

        float4 g = reinterpret_cast<const float4*>(gamma)[n4];
        float4 b = reinterpret_cast<const float4*>(beta)[n4];
        float4 y;
        y.x = (v.x - mu) * rstd * g.x + b.x;
        y.y = (v.y - mu) * rstd * g.y + b.y;
        y.z = (v.z - mu) * rstd * g.z + b.z;
        y.w = (v.w - mu) * rstd * g.w + b.w;
        if (RELU) {
            y.x = fmaxf(y.x, 0.f); y.y = fmaxf(y.y, 0.f);
            y.z = fmaxf(y.z, 0.f); y.w = fmaxf(y.w, 0.f);
        }
        reinterpret_cast<float4*>(outp)[(size_t)mrow * (E / 4) + n4] = y;
    }
}

// ============================================================
// launcher — 3 launches
// ============================================================
extern "C" void kernel_launch(void* const* d_in, const int* in_sizes, int n_in,
                              void* d_out, int out_size)
{
    const float* emb = (const float*)d_in[0];
    const float* W1  = (const float*)d_in[1];
    const float* b1  = (const float*)d_in[2];
    const float* g1  = (const float*)d_in[3];
    const float* be1 = (const float*)d_in[4];
    const float* W2  = (const float*)d_in[5];
    const float* b2  = (const float*)d_in[6];
    const float* g2  = (const float*)d_in[7];
    const float* be2 = (const float*)d_in[8];
    const int*   bp  = (const int*)d_in[9];

    float* out = (float*)d_out;
    float* out_joint = out;                      // [17][4096]
    float* out_bone  = out + (size_t)J * E;      // [16][4096]

    float*    h_p;   cudaGetSymbolAddress((void**)&h_p, d_h);
    unsigned* ctr_p; cudaGetSymbolAddress((void**)&ctr_p, d_ctr);

    // 1. normalize joints -> output head (+ zero sync counters)
    normalize_kernel<<<J, 256>>>(emb, out_joint);

    // 2. layer 1: gather-pair GEMM + LN + ReLU -> h
    layer_kernel<TK1, 0, true><<<dim3(4, NSLAB), 256>>>(
        W1, out_joint, bp, b1, g1, be1, h_p, ctr_p + 0, ctr_p + 1);

    // 3. layer 2: GEMM + LN -> bone features
    layer_kernel<TK2, 1, false><<<dim3(4, NSLAB), 256>>>(
        W2, h_p, nullptr, b2, g2, be2, out_bone, ctr_p + 2, ctr_p + 3);
}

// round 7
// speedup vs baseline: 1.7241x; 1.7241x over previous
#include <cuda_runtime.h>
#include <cstdint>

#define J   17
#define E   4096
#define M16 16
#define K1  (2*E)       // 8192
#define K2  E           // 4096
#define TK1 128         // GEMM1: 64 slabs
#define TK2 64          // GEMM2: 64 slabs
#define KS  64
#define LN_EPS 1e-5f

typedef unsigned long long ull;

// -------- device scratch --------
__device__ float  d_h[M16 * E];             // 256 KB hidden (linear)
__device__ float  d_partial[KS * M16 * E];  // 16 MB
__device__ float  d_sums[M16 * E];          // 256 KB
__device__ float2 d_stats[M16 * 4];

__device__ __forceinline__ void fma2(ull& d, ull a, ull b) {
    asm("fma.rn.f32x2 %0, %1, %2, %0;" : "+l"(d) : "l"(a), "l"(b));
}
__device__ __forceinline__ ull dup_pack(float p) {
    unsigned int u = __float_as_uint(p);
    return ((ull)u << 32) | (ull)u;
}

union U16 { uint4 u; ulonglong2 l; };

// ============================================================
// L2-normalize joints, scale by sqrt(E)=64. grid=17, block=256.
// ============================================================
__global__ void __launch_bounds__(256) normalize_kernel(
    const float* __restrict__ x, float* __restrict__ out_joint)
{
    int row = blockIdx.x;
    int tid = threadIdx.x;
    const float4* xr4 = reinterpret_cast<const float4*>(x + (size_t)row * E);

    float4 v[4];
    float s = 0.f;
    #pragma unroll
    for (int i = 0; i < 4; i++) {
        v[i] = xr4[tid + i * 256];
        s += v[i].x * v[i].x + v[i].y * v[i].y
           + v[i].z * v[i].z + v[i].w * v[i].w;
    }
    __shared__ float red[256];
    red[tid] = s;
    __syncthreads();
    for (int off = 128; off > 0; off >>= 1) {
        if (tid < off) red[tid] += red[tid + off];
        __syncthreads();
    }
    __shared__ float s_inv;
    if (tid == 0) s_inv = 64.0f / fmaxf(sqrtf(red[0]), 1e-12f);
    __syncthreads();
    float inv = s_inv;
    float4* o4 = reinterpret_cast<float4*>(out_joint + (size_t)row * E);
    #pragma unroll
    for (int i = 0; i < 4; i++) {
        float4 y;
        y.x = v[i].x * inv; y.y = v[i].y * inv;
        y.z = v[i].z * inv; y.w = v[i].w * inv;
        o4[tid + i * 256] = y;
    }
}

// ============================================================
// Split-K GEMM. out[m][n] = sum_k act[k][m] * W[k][n]
// grid=(4, K/TK), block=256, 2 CTAs/SM.
// Warp w: m-half (w&1)*8 bones, col-block (w>>1): 8 cols/thread.
// Double-buffered W prefetch (2 rows/stage), streaming loads.
// MODE 0: gather pairs from joint+bone_pairs; MODE 1: from linear h.
// ============================================================
template<int TK, int MODE>
__global__ void __launch_bounds__(256, 2) gemm_splitk(
    const float* __restrict__ W,
    const float* __restrict__ act,
    const int*   __restrict__ bp,
    float* __restrict__ partial)
{
    __shared__ ull sp[TK * M16];

    int tid = threadIdx.x;
    int k0 = blockIdx.y * TK;

    // ---- activation slab fill (gather + duplicate) ----
    {
        int m = tid & 15;
        const float* r0;
        const float* r1;
        if (MODE == 0) {
            r0 = act + (size_t)bp[2 * m] * E;
            r1 = act + (size_t)bp[2 * m + 1] * E;
        } else {
            r0 = act + (size_t)m * E;
            r1 = r0;
        }
        #pragma unroll
        for (int i = 0; i < (TK * M16) / 256; i++) {
            int kl = (tid >> 4) + i * 16;
            int k = k0 + kl;
            float p;
            if (MODE == 0) {
                int col = k & (E - 1);
                p = (k < E) ? r0[col] : r1[col];
            } else {
                p = r0[k];
            }
            sp[kl * M16 + m] = dup_pack(p);
        }
    }
    __syncthreads();

    int wid  = tid >> 5;
    int lane = tid & 31;
    int mh   = (wid & 1) * 8;
    int n    = blockIdx.x * 1024 + (wid >> 1) * 256 + lane * 8;
    const float* wp = W + (size_t)k0 * E + n;

    ull acc[8][4];
    #pragma unroll
    for (int m = 0; m < 8; m++)
        #pragma unroll
        for (int c = 0; c < 4; c++) acc[m][c] = 0ULL;

    struct Row { U16 a, b; };
    Row ra[2], rb[2];

    #define LOADROW(DST, R) {                                                 \
        const uint4* wr = reinterpret_cast<const uint4*>(wp + (size_t)(R) * E); \
        (DST).a.u = __ldcs(wr);                                               \
        (DST).b.u = __ldcs(wr + 1);                                           \
    }

    #define CONSUME(RW, K) {                                                  \
        const ulonglong2* srow =                                              \
            reinterpret_cast<const ulonglong2*>(sp + (K) * M16 + mh);         \
        _Pragma("unroll")                                                     \
        for (int q = 0; q < 4; q++) {                                         \
            ulonglong2 p = srow[q];                                           \
            fma2(acc[2*q  ][0], (RW).a.l.x, p.x);                             \
            fma2(acc[2*q  ][1], (RW).a.l.y, p.x);                             \
            fma2(acc[2*q  ][2], (RW).b.l.x, p.x);                             \
            fma2(acc[2*q  ][3], (RW).b.l.y, p.x);                             \
            fma2(acc[2*q+1][0], (RW).a.l.x, p.y);                             \
            fma2(acc[2*q+1][1], (RW).a.l.y, p.y);                             \
            fma2(acc[2*q+1][2], (RW).b.l.x, p.y);                             \
            fma2(acc[2*q+1][3], (RW).b.l.y, p.y);                             \
        }                                                                     \
    }

    LOADROW(ra[0], 0)
    LOADROW(ra[1], 1)

    #pragma unroll 1
    for (int kb = 0; kb < TK - 4; kb += 4) {
        LOADROW(rb[0], kb + 2)
        LOADROW(rb[1], kb + 3)
        CONSUME(ra[0], kb)
        CONSUME(ra[1], kb + 1)
        LOADROW(ra[0], kb + 4)
        LOADROW(ra[1], kb + 5)
        CONSUME(rb[0], kb + 2)
        CONSUME(rb[1], kb + 3)
    }
    LOADROW(rb[0], TK - 2)
    LOADROW(rb[1], TK - 1)
    CONSUME(ra[0], TK - 4)
    CONSUME(ra[1], TK - 3)
    CONSUME(rb[0], TK - 2)
    CONSUME(rb[1], TK - 1)

    #undef LOADROW
    #undef CONSUME

    // ---- write partials [slab][m][E], streaming stores ----
    size_t base = ((size_t)blockIdx.y * M16 + mh) * E + n;
    #pragma unroll
    for (int m = 0; m < 8; m++) {
        U16 o0, o1;
        o0.l.x = acc[m][0]; o0.l.y = acc[m][1];
        o1.l.x = acc[m][2]; o1.l.y = acc[m][3];
        __stcs(reinterpret_cast<uint4*>(&partial[base + (size_t)m * E]),     o0.u);
        __stcs(reinterpret_cast<uint4*>(&partial[base + (size_t)m * E + 4]), o1.u);
    }
}

// ============================================================
// Split-K reduce + bias (float4), per-chunk LN stats.
// grid = (4, 16), block=256.
// ============================================================
__global__ void __launch_bounds__(256) splitk_reduce_kernel(
    const float4* __restrict__ partial4,
    const float4* __restrict__ bias4,
    float4* __restrict__ sums4, float2* __restrict__ stats)
{
    int m   = blockIdx.y;
    int tid = threadIdx.x;
    int n4  = blockIdx.x * 256 + tid;

    const float4* p = partial4 + (size_t)m * (E / 4) + n4;
    const size_t stride = (size_t)M16 * (E / 4);

    float4 a[8];
    a[0] = bias4[n4];
    #pragma unroll
    for (int r = 1; r < 8; r++) a[r] = make_float4(0.f, 0.f, 0.f, 0.f);

    #pragma unroll
    for (int ks = 0; ks < KS; ks += 8) {
        #pragma unroll
        for (int r = 0; r < 8; r++) {
            float4 v = __ldcs(&p[(size_t)(ks + r) * stride]);
            a[r].x += v.x; a[r].y += v.y; a[r].z += v.z; a[r].w += v.w;
        }
    }
    #pragma unroll
    for (int r = 4; r > 0; r >>= 1)
        #pragma unroll
        for (int s = 0; s < r; s++) {
            a[s].x += a[s + r].x; a[s].y += a[s + r].y;
            a[s].z += a[s + r].z; a[s].w += a[s + r].w;
        }
    float4 v = a[0];
    sums4[(size_t)m * (E / 4) + n4] = v;

    __shared__ float rs[256], rq[256];
    rs[tid] = (v.x + v.y) + (v.z + v.w);
    rq[tid] = (v.x * v.x + v.y * v.y) + (v.z * v.z + v.w * v.w);
    __syncthreads();
    for (int off = 128; off > 0; off >>= 1) {
        if (tid < off) { rs[tid] += rs[tid + off]; rq[tid] += rq[tid + off]; }
        __syncthreads();
    }
    if (tid == 0)
        stats[m * 4 + blockIdx.x] = make_float2(rs[0], rq[0]);
}

// ============================================================
// Apply LN (+ReLU), linear coalesced float4 output.
// grid = (4, 16), block=256.
// ============================================================
template<bool RELU>
__global__ void __launch_bounds__(256) apply_ln_kernel(
    const float4* __restrict__ sums4,
    const float2* __restrict__ stats,
    const float4* __restrict__ gamma4,
    const float4* __restrict__ beta4,
    float4* __restrict__ out4)
{
    int m  = blockIdx.y;
    int n4 = blockIdx.x * 256 + threadIdx.x;

    float2 s0 = stats[m * 4 + 0];
    float2 s1 = stats[m * 4 + 1];
    float2 s2 = stats[m * 4 + 2];
    float2 s3 = stats[m * 4 + 3];
    float sum = (s0.x + s1.x) + (s2.x + s3.x);
    float sq  = (s0.y + s1.y) + (s2.y + s3.y);
    float mu   = sum * (1.0f / E);
    float var  = sq * (1.0f / E) - mu * mu;
    float rstd = rsqrtf(var + LN_EPS);

    float4 v = sums4[(size_t)m * (E / 4) + n4];
    float4 g = gamma4[n4];
    float4 b = beta4[n4];
    float4 y;
    y.x = (v.x - mu) * rstd * g.x + b.x;
    y.y = (v.y - mu) * rstd * g.y + b.y;
    y.z = (v.z - mu) * rstd * g.z + b.z;
    y.w = (v.w - mu) * rstd * g.w + b.w;
    if (RELU) {
        y.x = fmaxf(y.x, 0.f); y.y = fmaxf(y.y, 0.f);
        y.z = fmaxf(y.z, 0.f); y.w = fmaxf(y.w, 0.f);
    }
    out4[(size_t)m * (E / 4) + n4] = y;
}

// ============================================================
// launcher — 7 launches
// ============================================================
extern "C" void kernel_launch(void* const* d_in, const int* in_sizes, int n_in,
                              void* d_out, int out_size)
{
    const float* emb = (const float*)d_in[0];
    const float* W1  = (const float*)d_in[1];
    const float* b1  = (const float*)d_in[2];
    const float* g1  = (const float*)d_in[3];
    const float* be1 = (const float*)d_in[4];
    const float* W2  = (const float*)d_in[5];
    const float* b2  = (const float*)d_in[6];
    const float* g2  = (const float*)d_in[7];
    const float* be2 = (const float*)d_in[8];
    const int*   bp  = (const int*)d_in[9];

    float* out = (float*)d_out;
    float* out_joint = out;                      // [17][4096]
    float* out_bone  = out + (size_t)J * E;      // [16][4096]

    float*  h_p;       cudaGetSymbolAddress((void**)&h_p, d_h);
    float*  partial_p; cudaGetSymbolAddress((void**)&partial_p, d_partial);
    float*  sums_p;    cudaGetSymbolAddress((void**)&sums_p, d_sums);
    float2* stats_p;   cudaGetSymbolAddress((void**)&stats_p, d_stats);

    // 1. normalize joints -> output head (gather source for GEMM1)
    normalize_kernel<<<J, 256>>>(emb, out_joint);

    // 2. GEMM1 split-K (pair gather fused)
    gemm_splitk<TK1, 0><<<dim3(4, K1 / TK1), 256>>>(
        W1, out_joint, bp, partial_p);

    // 3-4. reduce + bias; apply LN+ReLU -> h
    splitk_reduce_kernel<<<dim3(4, M16), 256>>>(
        (const float4*)partial_p, (const float4*)b1, (float4*)sums_p, stats_p);
    apply_ln_kernel<true><<<dim3(4, M16), 256>>>(
        (const float4*)sums_p, stats_p, (const float4*)g1, (const float4*)be1,
        (float4*)h_p);

    // 5. GEMM2 split-K (h gather fused)
    gemm_splitk<TK2, 1><<<dim3(4, K2 / TK2), 256>>>(
        W2, h_p, nullptr, partial_p);

    // 6-7. reduce + bias; apply LN -> final bone features
    splitk_reduce_kernel<<<dim3(4, M16), 256>>>(
        (const float4*)partial_p, (const float4*)b2, (float4*)sums_p, stats_p);
    apply_ln_kernel<false><<<dim3(4, M16), 256>>>(
        (const float4*)sums_p, stats_p, (const float4*)g2, (const float4*)be2,
        (float4*)out_bone);
}